// round 2
// baseline (speedup 1.0000x reference)
#include <cuda_runtime.h>
#include <math.h>

#define LTOK 31744          // 31*32*32
#define DI   128
#define DS   16
#define NXP  36             // DT_RANK + 2*DS
#define LC   32             // scan chunk length
#define NCH  (LTOK/LC)      // 992
#define NT   (LTOK/64)      // 496 token tiles of 64

// ---- scratch layout (floats) ----
#define L64  (LTOK*64)
#define L128 (LTOK*128)
#define L256 (LTOK*256)
#define L32  (LTOK*32)
#define PSZ  (NCH*DI*DS)

#define OFF_XIZ   0
#define OFF_XC    (OFF_XIZ + L256)
#define OFF_DELTA (OFF_XC + L128)
#define OFF_BC    (OFF_DELTA + L128)
#define OFF_P     (OFF_BC + L32)
#define OFF_S     (OFF_P + PSZ)
#define OFF_H0    (OFF_S + PSZ)
#define OFF_YZ    (OFF_H0 + PSZ)
#define OFF_XT2   (OFF_YZ + L128)
#define OFF_HN    (OFF_XT2 + L64)
#define OFF_GG    (OFF_HN + L64)
#define SCRATCH_TOTAL (OFF_GG + L128)

__device__ float g_scratch[SCRATCH_TOTAL];

// ============================================================
// Persistent register-tiled GEMM: Y[L,N] = X[L,K] @ W[K,N]
// LNIN=1: X is raw x in [C=64, L] layout; tile is transposed+LayerNormed
//         (lw/lb = ln1 params) before the mainloop. K must be 64.
// EPI 0: plain store
// EPI 1: gated FFN1: Y[l,c] = silu(o[l,c]) * o[l,c+128]
// EPI 2: out-proj: v = acc + residual; Y=v; Y2=LN(v)*lw+lb
//        RTR=1: residual R is in [C, L] layout (raw x), loaded transposed
// EPI 3: final: v = acc + R([L,64]); Y[c*L + l] = v (transposed out)
// ============================================================
template<int K, int N, int RC, int EPI, int LNIN, int RTR>
__global__ void k_gemm(const float* __restrict__ X, const float* __restrict__ W,
                       float* __restrict__ Y, const float* __restrict__ R,
                       const float* __restrict__ lw, const float* __restrict__ lb,
                       float* __restrict__ Y2)
{
    extern __shared__ float sm[];
    float* sW  = sm;                    // K*N
    float* sX  = sm + K * N;            // 64*K  (reused as sT 64x65 in EPI 2/3)
    float* sAux = sm + K * N + 64 * K;  // 64*65 (sTmp for LNIN, sR for EPI 2/3)
    int tid = threadIdx.x, tx = tid & 31, ty = tid >> 5;

    for (int i = tid; i < K * N; i += 256) sW[i] = W[i];
    __syncthreads();

    for (int tile = blockIdx.x; tile < NT; tile += gridDim.x) {
        int l0 = tile * 64;

        if (LNIN) {
            // load x tile transposed: sAux[i][c]
            for (int idx = tid; idx < 4096; idx += 256) {
                int c = idx >> 6, i = idx & 63;
                sAux[i * 65 + c] = X[c * LTOK + l0 + i];
            }
            __syncthreads();
            // 4 threads per row: partial sums + shfl combine
            int r = tid >> 2, q = tid & 3;
            float s = 0.f, ss = 0.f;
            #pragma unroll
            for (int c = q * 16; c < q * 16 + 16; c++) {
                float v = sAux[r * 65 + c]; s += v; ss += v * v;
            }
            s  += __shfl_xor_sync(~0u, s, 1);  ss += __shfl_xor_sync(~0u, ss, 1);
            s  += __shfl_xor_sync(~0u, s, 2);  ss += __shfl_xor_sync(~0u, ss, 2);
            float mu = s * (1.f / 64.f);
            float rs = rsqrtf(ss * (1.f / 64.f) - mu * mu + 1e-5f);
            #pragma unroll
            for (int c = q * 16; c < q * 16 + 16; c++)
                sX[r * 64 + c] = (sAux[r * 65 + c] - mu) * rs * lw[c] + lb[c];
        } else {
            for (int i = tid; i < 64 * K; i += 256) sX[i] = X[l0 * K + i];
        }
        if (EPI >= 2) {
            if (RTR) {
                for (int idx = tid; idx < 4096; idx += 256) {
                    int c = idx >> 6, i = idx & 63;
                    sAux[i * 65 + c] = R[c * LTOK + l0 + i];
                }
            } else {
                for (int idx = tid; idx < 4096; idx += 256) {
                    int r = idx >> 6, c = idx & 63;
                    sAux[r * 65 + c] = R[(l0 + r) * 64 + c];
                }
            }
        }
        __syncthreads();

        float acc[8][RC];
        #pragma unroll
        for (int i = 0; i < 8; i++)
            #pragma unroll
            for (int j = 0; j < RC; j++) acc[i][j] = 0.f;

        #pragma unroll 2
        for (int k4 = 0; k4 < K; k4 += 4) {
            float4 xv[8];
            #pragma unroll
            for (int i = 0; i < 8; i++)
                xv[i] = *reinterpret_cast<const float4*>(&sX[(ty * 8 + i) * K + k4]);
            #pragma unroll
            for (int kk = 0; kk < 4; kk++) {
                float wv[RC];
                #pragma unroll
                for (int j = 0; j < RC; j++) wv[j] = sW[(k4 + kk) * N + tx + 32 * j];
                #pragma unroll
                for (int i = 0; i < 8; i++) {
                    float xs = (kk == 0) ? xv[i].x : (kk == 1) ? xv[i].y
                             : (kk == 2) ? xv[i].z : xv[i].w;
                    #pragma unroll
                    for (int j = 0; j < RC; j++) acc[i][j] = fmaf(xs, wv[j], acc[i][j]);
                }
            }
        }
        __syncthreads();

        if (EPI == 0) {
            #pragma unroll
            for (int i = 0; i < 8; i++)
                #pragma unroll
                for (int j = 0; j < RC; j++)
                    Y[(l0 + ty * 8 + i) * N + tx + 32 * j] = acc[i][j];
        } else if (EPI == 1) {
            #pragma unroll
            for (int i = 0; i < 8; i++)
                #pragma unroll
                for (int j = 0; j < 4; j++) {
                    float g = acc[i][j], v = acc[i][j + 4];
                    float sg = g / (1.f + __expf(-g));
                    Y[(l0 + ty * 8 + i) * 128 + tx + 32 * j] = sg * v;
                }
        } else {
            float* sT = sX;  // 64 x 65 (sX is free after mainloop)
            #pragma unroll
            for (int i = 0; i < 8; i++)
                #pragma unroll
                for (int j = 0; j < RC; j++) {
                    int row = ty * 8 + i, col = tx + 32 * j;
                    sT[row * 65 + col] = acc[i][j] + sAux[row * 65 + col];
                }
            __syncthreads();
            if (EPI == 2) {
                int r = tid >> 2, q = tid & 3;
                float s = 0.f, ss = 0.f;
                #pragma unroll
                for (int c = q * 16; c < q * 16 + 16; c++) {
                    float v = sT[r * 65 + c]; s += v; ss += v * v;
                }
                s  += __shfl_xor_sync(~0u, s, 1);  ss += __shfl_xor_sync(~0u, ss, 1);
                s  += __shfl_xor_sync(~0u, s, 2);  ss += __shfl_xor_sync(~0u, ss, 2);
                float mu = s * (1.f / 64.f);
                float rs = rsqrtf(ss * (1.f / 64.f) - mu * mu + 1e-5f);
                #pragma unroll
                for (int c = q * 16; c < q * 16 + 16; c++) {
                    float v = sT[r * 65 + c];
                    Y[(l0 + r) * 64 + c]  = v;
                    Y2[(l0 + r) * 64 + c] = (v - mu) * rs * lw[c] + lb[c];
                }
            } else {  // EPI == 3: transposed final store
                for (int idx = tid; idx < 4096; idx += 256) {
                    int ll = idx & 63, c = idx >> 6;
                    Y[c * LTOK + l0 + ll] = sT[ll * 65 + c];
                }
            }
            __syncthreads();
        }
    }
}

// ============================================================
// K3: causal depthwise conv(4) + ReLU, then xc@W_xproj -> (dt,B,C),
//     then delta = softplus(dt@W_dt + bias)
// ============================================================
__global__ void k_conv(const float* __restrict__ xiz, const float* __restrict__ cw,
                       const float* __restrict__ Wxp, const float* __restrict__ Wdt,
                       const float* __restrict__ bias,
                       float* __restrict__ xc, float* __restrict__ delta,
                       float* __restrict__ bcout)
{
    extern __shared__ float sm[];
    float* sxc  = sm;               // 64*128
    float* sWx  = sxc + 8192;       // 128*36
    float* sdbl = sWx + 4608;       // 64*36
    float* sWdt = sdbl + 2304;      // 4*128
    int tid = threadIdx.x;
    int l0 = blockIdx.x * 64;

    for (int i = tid; i < 4608; i += 256) sWx[i] = Wxp[i];
    for (int i = tid; i < 512; i += 256) sWdt[i] = Wdt[i];

    for (int idx = tid; idx < 8192; idx += 256) {
        int t = idx >> 7, d = idx & 127;
        int l = l0 + t;
        float acc = 0.f;
        #pragma unroll
        for (int j = 0; j < 4; j++) {
            int ls = l - 3 + j;
            float v = (ls >= 0) ? xiz[ls * 256 + d] : 0.f;
            acc = fmaf(cw[d * 4 + j], v, acc);
        }
        acc = fmaxf(acc, 0.f);
        sxc[t * 128 + d] = acc;
        xc[l * 128 + d] = acc;
    }
    __syncthreads();

    for (int idx = tid; idx < 64 * NXP; idx += 256) {
        int t = idx / NXP, n = idx % NXP;
        float acc = 0.f;
        #pragma unroll 8
        for (int dd = 0; dd < 128; dd++) acc = fmaf(sxc[t * 128 + dd], sWx[dd * NXP + n], acc);
        sdbl[t * NXP + n] = acc;
        if (n >= 4) bcout[(l0 + t) * 32 + (n - 4)] = acc;
    }
    __syncthreads();

    for (int idx = tid; idx < 8192; idx += 256) {
        int t = idx >> 7, d = idx & 127;
        float acc = bias[d];
        #pragma unroll
        for (int r = 0; r < 4; r++) acc = fmaf(sdbl[t * NXP + r], sWdt[r * 128 + d], acc);
        float sp = (acc > 20.f) ? acc : log1pf(__expf(acc));
        delta[(l0 + t) * 128 + d] = sp;
    }
}

// ============================================================
// Scan helpers: dA_s = exp(delta*A[s]); fast path uses A[s]=(s+1)*A[0]
// ============================================================
__device__ __forceinline__ void compute_dA(float dl, float A0, const float* A,
                                           bool fast, float (&dA)[DS])
{
    if (fast) {
        float r = __expf(dl * A0);
        float r2 = r * r, r4 = r2 * r2, r8 = r4 * r4;
        dA[0] = r;        dA[1] = r2;       dA[2] = r2 * r;     dA[3] = r4;
        dA[4] = r4 * r;   dA[5] = r4 * r2;  dA[6] = r4 * dA[2]; dA[7] = r8;
        dA[8] = r8 * r;   dA[9] = r8 * r2;  dA[10] = r8 * dA[2]; dA[11] = r8 * r4;
        dA[12] = r8 * dA[4]; dA[13] = r8 * dA[5]; dA[14] = r8 * dA[6]; dA[15] = r8 * r8;
    } else {
        #pragma unroll
        for (int s = 0; s < DS; s++) dA[s] = __expf(dl * A[s]);
    }
}

__device__ __forceinline__ bool load_A(const float* __restrict__ Alog, int d,
                                       float (&A)[DS], float& A0)
{
    #pragma unroll
    for (int s = 0; s < DS; s++) A[s] = -__expf(Alog[d * DS + s]);
    A0 = A[0];
    bool fast = (A0 < 0.f);
    #pragma unroll
    for (int s = 0; s < DS; s++) {
        float t = (float)(s + 1) * A0;
        fast = fast && (fabsf(A[s] - t) <= 1e-3f * fabsf(t));
    }
    return fast;
}

// K4: per-chunk local scan -> chunk product P, chunk sum S
__global__ void k_scan1(const float* __restrict__ delta, const float* __restrict__ u,
                        const float* __restrict__ bc, const float* __restrict__ Alog,
                        float* __restrict__ Pg, float* __restrict__ Sg)
{
    __shared__ float sB[LC * DS];
    int c = blockIdx.x, d = threadIdx.x;
    int l0 = c * LC;
    for (int idx = d; idx < LC * DS; idx += 128) {
        int t = idx >> 4, s = idx & 15;
        sB[idx] = bc[(l0 + t) * 32 + s];
    }
    __syncthreads();

    float A[DS], A0;
    bool fast = load_A(Alog, d, A, A0);

    float P[DS], S[DS];
    #pragma unroll
    for (int s = 0; s < DS; s++) { P[s] = 1.f; S[s] = 0.f; }

    #pragma unroll 2
    for (int t = 0; t < LC; t++) {
        float dl = delta[(l0 + t) * DI + d];
        float uu = u[(l0 + t) * DI + d];
        float du = dl * uu;
        float dA[DS];
        compute_dA(dl, A0, A, fast, dA);
        #pragma unroll
        for (int s = 0; s < DS; s++) {
            S[s] = fmaf(dA[s], S[s], du * sB[t * DS + s]);
            P[s] *= dA[s];
        }
    }
    int base = (c * DI + d) * DS;
    #pragma unroll
    for (int s = 0; s < DS; s++) { Pg[base + s] = P[s]; Sg[base + s] = S[s]; }
}

// K5: sequential carry across chunks per (d,s)
__global__ void k_carry(const float* __restrict__ Pg, const float* __restrict__ Sg,
                        float* __restrict__ H0)
{
    int i = blockIdx.x * blockDim.x + threadIdx.x;
    if (i >= DI * DS) return;
    float H = 0.f;
    for (int c = 0; c < NCH; c++) {
        int o = c * DI * DS + i;
        H0[o] = H;
        H = fmaf(Pg[o], H, Sg[o]);
    }
}

// K6: rescan with carry, emit yz = (y + u*D) * silu(z)
__global__ void k_scan2(const float* __restrict__ delta, const float* __restrict__ u,
                        const float* __restrict__ bc, const float* __restrict__ Alog,
                        const float* __restrict__ H0, const float* __restrict__ Dp,
                        const float* __restrict__ xiz, float* __restrict__ yz)
{
    __shared__ float sB[LC * DS], sC[LC * DS];
    int c = blockIdx.x, d = threadIdx.x;
    int l0 = c * LC;
    for (int idx = d; idx < LC * DS; idx += 128) {
        int t = idx >> 4, s = idx & 15;
        sB[idx] = bc[(l0 + t) * 32 + s];
        sC[idx] = bc[(l0 + t) * 32 + 16 + s];
    }
    __syncthreads();

    float A[DS], A0;
    bool fast = load_A(Alog, d, A, A0);

    float h[DS];
    #pragma unroll
    for (int s = 0; s < DS; s++) h[s] = H0[(c * DI + d) * DS + s];
    float Dd = Dp[d];

    #pragma unroll 2
    for (int t = 0; t < LC; t++) {
        float dl = delta[(l0 + t) * DI + d];
        float uu = u[(l0 + t) * DI + d];
        float du = dl * uu;
        float dA[DS];
        compute_dA(dl, A0, A, fast, dA);
        float y = 0.f;
        #pragma unroll
        for (int s = 0; s < DS; s++) {
            h[s] = fmaf(dA[s], h[s], du * sB[t * DS + s]);
            y = fmaf(h[s], sC[t * DS + s], y);
        }
        y = fmaf(uu, Dd, y);
        float z = xiz[(l0 + t) * 256 + 128 + d];
        float sig = 1.f / (1.f + __expf(-z));
        yz[(l0 + t) * DI + d] = y * (z * sig);
    }
}

// ============================================================
// launch
// ============================================================
#define SM_G1 ((64 * 256 + 64 * 64 + 64 * 65) * 4)     // 98560
#define SM_F1 ((64 * 256 + 64 * 64) * 4)               // 81920
#define SM_G2 ((128 * 64 + 64 * 128 + 64 * 65) * 4)    // 82176
#define SM_CONV ((8192 + 4608 + 2304 + 512) * 4)       // 62464

extern "C" void kernel_launch(void* const* d_in, const int* in_sizes, int n_in,
                              void* d_out, int out_size)
{
    const float* x    = (const float*)d_in[0];
    const float* ln1w = (const float*)d_in[1];
    const float* ln1b = (const float*)d_in[2];
    const float* Win  = (const float*)d_in[3];
    const float* cw   = (const float*)d_in[4];
    const float* Wxp  = (const float*)d_in[5];
    const float* Wdt  = (const float*)d_in[6];
    const float* dtb  = (const float*)d_in[7];
    const float* Alog = (const float*)d_in[8];
    const float* Dssm = (const float*)d_in[9];
    const float* Wout = (const float*)d_in[10];
    const float* ln2w = (const float*)d_in[11];
    const float* ln2b = (const float*)d_in[12];
    const float* Wf1  = (const float*)d_in[13];
    const float* Wf2  = (const float*)d_in[14];
    float* out = (float*)d_out;

    float* sc = nullptr;
    cudaGetSymbolAddress((void**)&sc, g_scratch);

    float* xiz   = sc + OFF_XIZ;
    float* xc    = sc + OFF_XC;
    float* delta = sc + OFF_DELTA;
    float* bcb   = sc + OFF_BC;
    float* Pg    = sc + OFF_P;
    float* Sg    = sc + OFF_S;
    float* H0    = sc + OFF_H0;
    float* yzb   = sc + OFF_YZ;
    float* xt2   = sc + OFF_XT2;
    float* hn    = sc + OFF_HN;
    float* gg    = sc + OFF_GG;

    cudaFuncSetAttribute(k_gemm<64, 256, 8, 0, 1, 0>, cudaFuncAttributeMaxDynamicSharedMemorySize, SM_G1);
    cudaFuncSetAttribute(k_gemm<64, 256, 8, 1, 0, 0>, cudaFuncAttributeMaxDynamicSharedMemorySize, SM_F1);
    cudaFuncSetAttribute(k_gemm<128, 64, 2, 2, 0, 1>, cudaFuncAttributeMaxDynamicSharedMemorySize, SM_G2);
    cudaFuncSetAttribute(k_gemm<128, 64, 2, 3, 0, 0>, cudaFuncAttributeMaxDynamicSharedMemorySize, SM_G2);
    cudaFuncSetAttribute(k_conv, cudaFuncAttributeMaxDynamicSharedMemorySize, SM_CONV);

    // 1. (LN1 fused) x -> xn @ W_in -> xi | z
    k_gemm<64, 256, 8, 0, 1, 0><<<296, 256, SM_G1>>>(x, Win, xiz, nullptr, ln1w, ln1b, nullptr);
    // 2. conv + relu + xproj + delta
    k_conv<<<NT, 256, SM_CONV>>>(xiz, cw, Wxp, Wdt, dtb, xc, delta, bcb);
    // 3-5. chunked selective scan
    k_scan1<<<NCH, 128>>>(delta, xc, bcb, Alog, Pg, Sg);
    k_carry<<<8, 256>>>(Pg, Sg, H0);
    k_scan2<<<NCH, 128>>>(delta, xc, bcb, Alog, H0, Dssm, xiz, yzb);
    // 6. yz @ W_out + residual(x, transposed) -> xt2, LN2 -> hn
    k_gemm<128, 64, 2, 2, 0, 1><<<296, 256, SM_G2>>>(yzb, Wout, xt2, x, ln2w, ln2b, hn);
    // 7. hn @ W_ffn1, gated silu -> gg
    k_gemm<64, 256, 8, 1, 0, 0><<<296, 256, SM_F1>>>(hn, Wf1, gg, nullptr, nullptr, nullptr, nullptr);
    // 8. gg @ W_ffn2 + residual(xt2), transposed store -> out
    k_gemm<128, 64, 2, 3, 0, 0><<<296, 256, SM_G2>>>(gg, Wf2, out, xt2, nullptr, nullptr, nullptr);
}

// round 3
// speedup vs baseline: 1.2361x; 1.2361x over previous
#include <cuda_runtime.h>
#include <math.h>

#define LTOK 31744          // 31*32*32
#define DI   128
#define DS   16
#define NXP  36             // DT_RANK + 2*DS
#define LC   32             // scan chunk length
#define NCH  (LTOK/LC)      // 992
#define NT   (LTOK/64)      // 496 token tiles of 64
#define NSEQ (DI*DS)        // 2048
#define GRP  32             // chunks per carry group
#define NGRP (NCH/GRP)      // 31

// ---- scratch layout (floats) ----
#define L64  (LTOK*64)
#define L128 (LTOK*128)
#define L256 (LTOK*256)
#define L32  (LTOK*32)
#define PSZ  (NCH*NSEQ)
#define GSZ  (NGRP*NSEQ)

#define OFF_XIZ   0
#define OFF_XC    (OFF_XIZ + L256)
#define OFF_DELTA (OFF_XC + L128)
#define OFF_BC    (OFF_DELTA + L128)
#define OFF_P     (OFF_BC + L32)
#define OFF_S     (OFF_P + PSZ)
#define OFF_H0    (OFF_S + PSZ)
#define OFF_PA    (OFF_H0 + PSZ)
#define OFF_SA    (OFF_PA + GSZ)
#define OFF_G     (OFF_SA + GSZ)
#define OFF_YZ    (OFF_G + GSZ)
#define OFF_XT2   (OFF_YZ + L128)
#define OFF_HN    (OFF_XT2 + L64)
#define OFF_GG    (OFF_HN + L64)
#define SCRATCH_TOTAL (OFF_GG + L128)

__device__ float g_scratch[SCRATCH_TOTAL];

// ============================================================
// Persistent register-tiled GEMM: Y[L,N] = X[L,K] @ W[K,N]
// LNIN=1: X is raw x in [C=64, L] layout; tile transposed+LayerNormed.
// EPI 0: plain store
// EPI 1: gated FFN1: Y[l,c] = silu(o[l,c]) * o[l,c+128]
// EPI 2: out-proj: v = acc + residual; Y=v; Y2=LN(v)*lw+lb (RTR: R in [C,L])
// EPI 3: final: v = acc + R([L,64]); Y[c*L + l] = v
// ============================================================
template<int K, int N, int RC, int EPI, int LNIN, int RTR>
__global__ void k_gemm(const float* __restrict__ X, const float* __restrict__ W,
                       float* __restrict__ Y, const float* __restrict__ R,
                       const float* __restrict__ lw, const float* __restrict__ lb,
                       float* __restrict__ Y2)
{
    extern __shared__ float sm[];
    float* sW  = sm;                    // K*N
    float* sX  = sm + K * N;            // 64*K  (reused as sT 64x65 in EPI 2/3)
    float* sAux = sm + K * N + 64 * K;  // 64*65
    int tid = threadIdx.x, tx = tid & 31, ty = tid >> 5;

    for (int i = tid; i < K * N; i += 256) sW[i] = W[i];
    __syncthreads();

    for (int tile = blockIdx.x; tile < NT; tile += gridDim.x) {
        int l0 = tile * 64;

        if (LNIN) {
            for (int idx = tid; idx < 4096; idx += 256) {
                int c = idx >> 6, i = idx & 63;
                sAux[i * 65 + c] = X[c * LTOK + l0 + i];
            }
            __syncthreads();
            int r = tid >> 2, q = tid & 3;
            float s = 0.f, ss = 0.f;
            #pragma unroll
            for (int c = q * 16; c < q * 16 + 16; c++) {
                float v = sAux[r * 65 + c]; s += v; ss += v * v;
            }
            s  += __shfl_xor_sync(~0u, s, 1);  ss += __shfl_xor_sync(~0u, ss, 1);
            s  += __shfl_xor_sync(~0u, s, 2);  ss += __shfl_xor_sync(~0u, ss, 2);
            float mu = s * (1.f / 64.f);
            float rs = rsqrtf(ss * (1.f / 64.f) - mu * mu + 1e-5f);
            #pragma unroll
            for (int c = q * 16; c < q * 16 + 16; c++)
                sX[r * 64 + c] = (sAux[r * 65 + c] - mu) * rs * lw[c] + lb[c];
        } else {
            for (int i = tid; i < 64 * K; i += 256) sX[i] = X[l0 * K + i];
        }
        if (EPI >= 2) {
            if (RTR) {
                for (int idx = tid; idx < 4096; idx += 256) {
                    int c = idx >> 6, i = idx & 63;
                    sAux[i * 65 + c] = R[c * LTOK + l0 + i];
                }
            } else {
                for (int idx = tid; idx < 4096; idx += 256) {
                    int r = idx >> 6, c = idx & 63;
                    sAux[r * 65 + c] = R[(l0 + r) * 64 + c];
                }
            }
        }
        __syncthreads();

        float acc[8][RC];
        #pragma unroll
        for (int i = 0; i < 8; i++)
            #pragma unroll
            for (int j = 0; j < RC; j++) acc[i][j] = 0.f;

        #pragma unroll 2
        for (int k4 = 0; k4 < K; k4 += 4) {
            float4 xv[8];
            #pragma unroll
            for (int i = 0; i < 8; i++)
                xv[i] = *reinterpret_cast<const float4*>(&sX[(ty * 8 + i) * K + k4]);
            #pragma unroll
            for (int kk = 0; kk < 4; kk++) {
                float wv[RC];
                #pragma unroll
                for (int j = 0; j < RC; j++) wv[j] = sW[(k4 + kk) * N + tx + 32 * j];
                #pragma unroll
                for (int i = 0; i < 8; i++) {
                    float xs = (kk == 0) ? xv[i].x : (kk == 1) ? xv[i].y
                             : (kk == 2) ? xv[i].z : xv[i].w;
                    #pragma unroll
                    for (int j = 0; j < RC; j++) acc[i][j] = fmaf(xs, wv[j], acc[i][j]);
                }
            }
        }
        __syncthreads();

        if (EPI == 0) {
            #pragma unroll
            for (int i = 0; i < 8; i++)
                #pragma unroll
                for (int j = 0; j < RC; j++)
                    Y[(l0 + ty * 8 + i) * N + tx + 32 * j] = acc[i][j];
        } else if (EPI == 1) {
            #pragma unroll
            for (int i = 0; i < 8; i++)
                #pragma unroll
                for (int j = 0; j < 4; j++) {
                    float g = acc[i][j], v = acc[i][j + 4];
                    float sg = g / (1.f + __expf(-g));
                    Y[(l0 + ty * 8 + i) * 128 + tx + 32 * j] = sg * v;
                }
        } else {
            float* sT = sX;
            #pragma unroll
            for (int i = 0; i < 8; i++)
                #pragma unroll
                for (int j = 0; j < RC; j++) {
                    int row = ty * 8 + i, col = tx + 32 * j;
                    sT[row * 65 + col] = acc[i][j] + sAux[row * 65 + col];
                }
            __syncthreads();
            if (EPI == 2) {
                int r = tid >> 2, q = tid & 3;
                float s = 0.f, ss = 0.f;
                #pragma unroll
                for (int c = q * 16; c < q * 16 + 16; c++) {
                    float v = sT[r * 65 + c]; s += v; ss += v * v;
                }
                s  += __shfl_xor_sync(~0u, s, 1);  ss += __shfl_xor_sync(~0u, ss, 1);
                s  += __shfl_xor_sync(~0u, s, 2);  ss += __shfl_xor_sync(~0u, ss, 2);
                float mu = s * (1.f / 64.f);
                float rs = rsqrtf(ss * (1.f / 64.f) - mu * mu + 1e-5f);
                #pragma unroll
                for (int c = q * 16; c < q * 16 + 16; c++) {
                    float v = sT[r * 65 + c];
                    Y[(l0 + r) * 64 + c]  = v;
                    Y2[(l0 + r) * 64 + c] = (v - mu) * rs * lw[c] + lb[c];
                }
            } else {
                for (int idx = tid; idx < 4096; idx += 256) {
                    int ll = idx & 63, c = idx >> 6;
                    Y[c * LTOK + l0 + ll] = sT[ll * 65 + c];
                }
            }
            __syncthreads();
        }
    }
}

// ============================================================
// conv + relu + xproj + softplus(delta)
// ============================================================
__global__ void k_conv(const float* __restrict__ xiz, const float* __restrict__ cw,
                       const float* __restrict__ Wxp, const float* __restrict__ Wdt,
                       const float* __restrict__ bias,
                       float* __restrict__ xc, float* __restrict__ delta,
                       float* __restrict__ bcout)
{
    extern __shared__ float sm[];
    float* sxc  = sm;               // 64*128
    float* sWx  = sxc + 8192;       // 128*36
    float* sdbl = sWx + 4608;       // 64*36
    float* sWdt = sdbl + 2304;      // 4*128
    float* scw  = sWdt + 512;       // 512
    int tid = threadIdx.x;
    int l0 = blockIdx.x * 64;

    for (int i = tid; i < 4608; i += 256) sWx[i] = Wxp[i];
    for (int i = tid; i < 512; i += 256) { sWdt[i] = Wdt[i]; scw[i] = cw[i]; }
    __syncthreads();

    for (int idx = tid; idx < 8192; idx += 256) {
        int t = idx >> 7, d = idx & 127;
        int l = l0 + t;
        float acc = 0.f;
        #pragma unroll
        for (int j = 0; j < 4; j++) {
            int ls = l - 3 + j;
            float v = (ls >= 0) ? xiz[ls * 256 + d] : 0.f;
            acc = fmaf(scw[d * 4 + j], v, acc);
        }
        acc = fmaxf(acc, 0.f);
        sxc[t * 128 + d] = acc;
        xc[l * 128 + d] = acc;
    }
    __syncthreads();

    for (int idx = tid; idx < 64 * NXP; idx += 256) {
        int t = idx / NXP, n = idx % NXP;
        float acc = 0.f;
        #pragma unroll 8
        for (int dd = 0; dd < 128; dd++) acc = fmaf(sxc[t * 128 + dd], sWx[dd * NXP + n], acc);
        sdbl[t * NXP + n] = acc;
        if (n >= 4) bcout[(l0 + t) * 32 + (n - 4)] = acc;
    }
    __syncthreads();

    for (int idx = tid; idx < 8192; idx += 256) {
        int t = idx >> 7, d = idx & 127;
        float acc = bias[d];
        #pragma unroll
        for (int r = 0; r < 4; r++) acc = fmaf(sdbl[t * NXP + r], sWdt[r * 128 + d], acc);
        float sp = (acc > 20.f) ? acc : log1pf(__expf(acc));
        delta[(l0 + t) * 128 + d] = sp;
    }
}

// ============================================================
// Scan helpers
// ============================================================
__device__ __forceinline__ void compute_dA(float dl, float A0, const float* A,
                                           bool fast, float (&dA)[DS])
{
    if (fast) {
        float r = __expf(dl * A0);
        float r2 = r * r, r4 = r2 * r2, r8 = r4 * r4;
        dA[0] = r;        dA[1] = r2;       dA[2] = r2 * r;     dA[3] = r4;
        dA[4] = r4 * r;   dA[5] = r4 * r2;  dA[6] = r4 * dA[2]; dA[7] = r8;
        dA[8] = r8 * r;   dA[9] = r8 * r2;  dA[10] = r8 * dA[2]; dA[11] = r8 * r4;
        dA[12] = r8 * dA[4]; dA[13] = r8 * dA[5]; dA[14] = r8 * dA[6]; dA[15] = r8 * r8;
    } else {
        #pragma unroll
        for (int s = 0; s < DS; s++) dA[s] = __expf(dl * A[s]);
    }
}

__device__ __forceinline__ bool load_A(const float* __restrict__ Alog, int d,
                                       float (&A)[DS], float& A0)
{
    #pragma unroll
    for (int s = 0; s < DS; s++) A[s] = -__expf(Alog[d * DS + s]);
    A0 = A[0];
    bool fast = (A0 < 0.f);
    #pragma unroll
    for (int s = 0; s < DS; s++) {
        float t = (float)(s + 1) * A0;
        fast = fast && (fabsf(A[s] - t) <= 1e-3f * fabsf(t));
    }
    return fast;
}

// K: per-chunk local scan -> chunk product P (=exp(sumdl*A)), chunk sum S
__global__ void k_scan1(const float* __restrict__ delta, const float* __restrict__ u,
                        const float* __restrict__ bc, const float* __restrict__ Alog,
                        float* __restrict__ Pg, float* __restrict__ Sg)
{
    __shared__ float sD[LC * DI], sU[LC * DI], sB[LC * DS];
    int c = blockIdx.x, d = threadIdx.x;
    int l0 = c * LC;
    const float4* gD = (const float4*)(delta + l0 * DI);
    const float4* gU = (const float4*)(u + l0 * DI);
    #pragma unroll
    for (int k = 0; k < LC * DI / 4 / 128; k++) {
        ((float4*)sD)[d + k * 128] = gD[d + k * 128];
        ((float4*)sU)[d + k * 128] = gU[d + k * 128];
    }
    for (int idx = d; idx < LC * DS; idx += 128) {
        int t = idx >> 4, s = idx & 15;
        sB[idx] = bc[(l0 + t) * 32 + s];
    }
    __syncthreads();

    float A[DS], A0;
    bool fast = load_A(Alog, d, A, A0);

    float S[DS];
    #pragma unroll
    for (int s = 0; s < DS; s++) S[s] = 0.f;
    float sumdl = 0.f;

    #pragma unroll 4
    for (int t = 0; t < LC; t++) {
        float dl = sD[t * DI + d];
        float du = dl * sU[t * DI + d];
        sumdl += dl;
        float dA[DS];
        compute_dA(dl, A0, A, fast, dA);
        #pragma unroll
        for (int s = 0; s < DS; s++)
            S[s] = fmaf(dA[s], S[s], du * sB[t * DS + s]);
    }
    float P[DS];
    compute_dA(sumdl, A0, A, fast, P);
    int base = (c * DI + d) * DS;
    #pragma unroll
    for (int s = 0; s < DS; s++) { Pg[base + s] = P[s]; Sg[base + s] = S[s]; }
}

// Carry level 1: compose GRP chunks per group -> group aggregates
__global__ void k_carry1(const float* __restrict__ Pg, const float* __restrict__ Sg,
                         float* __restrict__ Pa, float* __restrict__ Sa)
{
    int idx = blockIdx.x * blockDim.x + threadIdx.x;   // 0 .. NGRP*NSEQ-1
    int g = idx / NSEQ, i = idx % NSEQ;
    float P = 1.f, S = 0.f;
    #pragma unroll 4
    for (int t = 0; t < GRP; t++) {
        int o = (g * GRP + t) * NSEQ + i;
        float p = Pg[o], s = Sg[o];
        S = fmaf(p, S, s);
        P *= p;
    }
    Pa[g * NSEQ + i] = P;
    Sa[g * NSEQ + i] = S;
}

// Carry level 2: serial scan over NGRP group aggregates -> group-start H (G)
__global__ void k_carry2(const float* __restrict__ Pa, const float* __restrict__ Sa,
                         float* __restrict__ G)
{
    int i = blockIdx.x * blockDim.x + threadIdx.x;     // 0 .. NSEQ-1
    float H = 0.f;
    for (int g = 0; g < NGRP; g++) {
        G[g * NSEQ + i] = H;
        H = fmaf(Pa[g * NSEQ + i], H, Sa[g * NSEQ + i]);
    }
}

// Carry level 3: expand group-start H to per-chunk H0
__global__ void k_carry3(const float* __restrict__ Pg, const float* __restrict__ Sg,
                         const float* __restrict__ G, float* __restrict__ H0)
{
    int idx = blockIdx.x * blockDim.x + threadIdx.x;
    int g = idx / NSEQ, i = idx % NSEQ;
    float H = G[g * NSEQ + i];
    #pragma unroll 4
    for (int t = 0; t < GRP; t++) {
        int o = (g * GRP + t) * NSEQ + i;
        H0[o] = H;
        H = fmaf(Pg[o], H, Sg[o]);
    }
}

// rescan with carry, emit yz = (y + u*D) * silu(z)
__global__ void k_scan2(const float* __restrict__ delta, const float* __restrict__ u,
                        const float* __restrict__ bc, const float* __restrict__ Alog,
                        const float* __restrict__ H0, const float* __restrict__ Dp,
                        const float* __restrict__ xiz, float* __restrict__ yz)
{
    __shared__ float sD[LC * DI], sU[LC * DI], sB[LC * DS], sC[LC * DS];
    int c = blockIdx.x, d = threadIdx.x;
    int l0 = c * LC;
    const float4* gD = (const float4*)(delta + l0 * DI);
    const float4* gU = (const float4*)(u + l0 * DI);
    #pragma unroll
    for (int k = 0; k < LC * DI / 4 / 128; k++) {
        ((float4*)sD)[d + k * 128] = gD[d + k * 128];
        ((float4*)sU)[d + k * 128] = gU[d + k * 128];
    }
    for (int idx = d; idx < LC * DS; idx += 128) {
        int t = idx >> 4, s = idx & 15;
        sB[idx] = bc[(l0 + t) * 32 + s];
        sC[idx] = bc[(l0 + t) * 32 + 16 + s];
    }
    __syncthreads();

    float A[DS], A0;
    bool fast = load_A(Alog, d, A, A0);

    float h[DS];
    #pragma unroll
    for (int s = 0; s < DS; s++) h[s] = H0[(c * DI + d) * DS + s];
    float Dd = Dp[d];

    #pragma unroll 2
    for (int t = 0; t < LC; t++) {
        float z = xiz[(l0 + t) * 256 + 128 + d];
        float dl = sD[t * DI + d];
        float uu = sU[t * DI + d];
        float du = dl * uu;
        float dA[DS];
        compute_dA(dl, A0, A, fast, dA);
        float y = 0.f;
        #pragma unroll
        for (int s = 0; s < DS; s++) {
            h[s] = fmaf(dA[s], h[s], du * sB[t * DS + s]);
            y = fmaf(h[s], sC[t * DS + s], y);
        }
        y = fmaf(uu, Dd, y);
        float sig = 1.f / (1.f + __expf(-z));
        yz[(l0 + t) * DI + d] = y * (z * sig);
    }
}

// ============================================================
// launch
// ============================================================
#define SM_G1 ((64 * 256 + 64 * 64 + 64 * 65) * 4)     // 98560
#define SM_F1 ((64 * 256 + 64 * 64) * 4)               // 81920
#define SM_G2 ((128 * 64 + 64 * 128 + 64 * 65) * 4)    // 82176
#define SM_CONV ((8192 + 4608 + 2304 + 512 + 512) * 4) // 64512

extern "C" void kernel_launch(void* const* d_in, const int* in_sizes, int n_in,
                              void* d_out, int out_size)
{
    const float* x    = (const float*)d_in[0];
    const float* ln1w = (const float*)d_in[1];
    const float* ln1b = (const float*)d_in[2];
    const float* Win  = (const float*)d_in[3];
    const float* cw   = (const float*)d_in[4];
    const float* Wxp  = (const float*)d_in[5];
    const float* Wdt  = (const float*)d_in[6];
    const float* dtb  = (const float*)d_in[7];
    const float* Alog = (const float*)d_in[8];
    const float* Dssm = (const float*)d_in[9];
    const float* Wout = (const float*)d_in[10];
    const float* ln2w = (const float*)d_in[11];
    const float* ln2b = (const float*)d_in[12];
    const float* Wf1  = (const float*)d_in[13];
    const float* Wf2  = (const float*)d_in[14];
    float* out = (float*)d_out;

    float* sc = nullptr;
    cudaGetSymbolAddress((void**)&sc, g_scratch);

    float* xiz   = sc + OFF_XIZ;
    float* xc    = sc + OFF_XC;
    float* delta = sc + OFF_DELTA;
    float* bcb   = sc + OFF_BC;
    float* Pg    = sc + OFF_P;
    float* Sg    = sc + OFF_S;
    float* H0    = sc + OFF_H0;
    float* Pa    = sc + OFF_PA;
    float* Sa    = sc + OFF_SA;
    float* Gb    = sc + OFF_G;
    float* yzb   = sc + OFF_YZ;
    float* xt2   = sc + OFF_XT2;
    float* hn    = sc + OFF_HN;
    float* gg    = sc + OFF_GG;

    cudaFuncSetAttribute(k_gemm<64, 256, 8, 0, 1, 0>, cudaFuncAttributeMaxDynamicSharedMemorySize, SM_G1);
    cudaFuncSetAttribute(k_gemm<64, 256, 8, 1, 0, 0>, cudaFuncAttributeMaxDynamicSharedMemorySize, SM_F1);
    cudaFuncSetAttribute(k_gemm<128, 64, 2, 2, 0, 1>, cudaFuncAttributeMaxDynamicSharedMemorySize, SM_G2);
    cudaFuncSetAttribute(k_gemm<128, 64, 2, 3, 0, 0>, cudaFuncAttributeMaxDynamicSharedMemorySize, SM_G2);
    cudaFuncSetAttribute(k_conv, cudaFuncAttributeMaxDynamicSharedMemorySize, SM_CONV);

    // 1. (LN1 fused) x -> xn @ W_in -> xi | z
    k_gemm<64, 256, 8, 0, 1, 0><<<296, 256, SM_G1>>>(x, Win, xiz, nullptr, ln1w, ln1b, nullptr);
    // 2. conv + relu + xproj + delta
    k_conv<<<NT, 256, SM_CONV>>>(xiz, cw, Wxp, Wdt, dtb, xc, delta, bcb);
    // 3. chunk-local scan
    k_scan1<<<NCH, 128>>>(delta, xc, bcb, Alog, Pg, Sg);
    // 4. hierarchical carry
    k_carry1<<<NGRP * NSEQ / 256, 256>>>(Pg, Sg, Pa, Sa);
    k_carry2<<<NSEQ / 256, 256>>>(Pa, Sa, Gb);
    k_carry3<<<NGRP * NSEQ / 256, 256>>>(Pg, Sg, Gb, H0);
    // 5. rescan + gate
    k_scan2<<<NCH, 128>>>(delta, xc, bcb, Alog, H0, Dssm, xiz, yzb);
    // 6. yz @ W_out + residual(x, transposed) -> xt2, LN2 -> hn
    k_gemm<128, 64, 2, 2, 0, 1><<<296, 256, SM_G2>>>(yzb, Wout, xt2, x, ln2w, ln2b, hn);
    // 7. hn @ W_ffn1, gated silu -> gg
    k_gemm<64, 256, 8, 1, 0, 0><<<296, 256, SM_F1>>>(hn, Wf1, gg, nullptr, nullptr, nullptr, nullptr);
    // 8. gg @ W_ffn2 + residual(xt2), transposed store -> out
    k_gemm<128, 64, 2, 3, 0, 0><<<296, 256, SM_G2>>>(gg, Wf2, out, xt2, nullptr, nullptr, nullptr);
}